// round 7
// baseline (speedup 1.0000x reference)
#include <cuda_runtime.h>
#include <cuda_bf16.h>
#include <stdint.h>

#define NUM_BINS 256
#define NCH 3
#define HW (512 * 512)           // elements per (b, c) plane
#define BATCH 16
#define CHUNKS 8                  // chunks per (b,c) plane
#define CHUNK_ELEMS (HW / CHUNKS) // 32768
#define THREADS 256
// per image: BATCH*NCH planes * CHUNKS chunks
#define BLOCKS_PER_IMG (BATCH * NCH * CHUNKS)   // 384
#define TOTAL_HIST (2 * NCH * NUM_BINS)         // 1536

__device__ unsigned int g_hist[TOTAL_HIST];

__global__ void hml_zero_kernel() {
    int i = blockIdx.x * blockDim.x + threadIdx.x;
    if (i < TOTAL_HIST) g_hist[i] = 0u;
}

__global__ __launch_bounds__(THREADS)
void hml_hist_kernel(const float* __restrict__ img1,
                     const float* __restrict__ img2) {
    __shared__ unsigned int sh[NUM_BINS];
    for (int i = threadIdx.x; i < NUM_BINS; i += THREADS) sh[i] = 0u;
    __syncthreads();

    int bx  = blockIdx.x;
    int img = bx / BLOCKS_PER_IMG;            // 0 or 1
    int r   = bx - img * BLOCKS_PER_IMG;      // 0..383
    int bc    = r / CHUNKS;                   // 0..47  (b*3 + c)
    int chunk = r - bc * CHUNKS;              // 0..7
    int c = bc % NCH;

    const float* src = (img == 0) ? img1 : img2;
    const float4* p = reinterpret_cast<const float4*>(
        src + (size_t)bc * HW + (size_t)chunk * CHUNK_ELEMS);

    const int n4 = CHUNK_ELEMS / 4;           // 8192 float4 per block
    #pragma unroll 4
    for (int i = threadIdx.x; i < n4; i += THREADS) {
        float4 v = p[i];
        float vals[4] = {v.x, v.y, v.z, v.w};
        #pragma unroll
        for (int k = 0; k < 4; k++) {
            float x = vals[k];
            if (x >= 0.0f && x <= 1.0f) {
                int bin = (int)floorf(x * (float)NUM_BINS);
                bin = bin > (NUM_BINS - 1) ? (NUM_BINS - 1) : bin;
                atomicAdd(&sh[bin], 1u);
            }
        }
    }
    __syncthreads();

    unsigned int* dst = &g_hist[(img * NCH + c) * NUM_BINS];
    for (int i = threadIdx.x; i < NUM_BINS; i += THREADS) {
        unsigned int v = sh[i];
        if (v) atomicAdd(&dst[i], v);
    }
}

__global__ __launch_bounds__(NUM_BINS)
void hml_loss_kernel(float* __restrict__ out) {
    __shared__ float s1[NUM_BINS];
    __shared__ float s2[NUM_BINS];
    __shared__ float red[NUM_BINS / 32];

    int t = threadIdx.x;
    float loss = 0.0f;

    for (int c = 0; c < NCH; c++) {
        float h1 = (float)g_hist[c * NUM_BINS + t];
        float h2 = (float)g_hist[(NCH + c) * NUM_BINS + t];
        s1[t] = h1;
        s2[t] = h2;
        __syncthreads();

        // Hillis-Steele inclusive scan over 256 threads
        #pragma unroll
        for (int off = 1; off < NUM_BINS; off <<= 1) {
            float a1 = (t >= off) ? s1[t - off] : 0.0f;
            float a2 = (t >= off) ? s2[t - off] : 0.0f;
            __syncthreads();
            s1[t] += a1;
            s2[t] += a2;
            __syncthreads();
        }

        float tot1 = s1[NUM_BINS - 1];
        float tot2 = s2[NUM_BINS - 1];
        float d = fabsf(s1[t] / tot1 - s2[t] / tot2);
        __syncthreads();

        // block reduce d
        #pragma unroll
        for (int o = 16; o > 0; o >>= 1)
            d += __shfl_down_sync(0xFFFFFFFFu, d, o);
        if ((t & 31) == 0) red[t >> 5] = d;
        __syncthreads();
        if (t == 0) {
            float s = 0.0f;
            #pragma unroll
            for (int w = 0; w < NUM_BINS / 32; w++) s += red[w];
            loss += s;
        }
        __syncthreads();
    }

    if (t == 0) out[0] = loss / 3.0f;
}

extern "C" void kernel_launch(void* const* d_in, const int* in_sizes, int n_in,
                              void* d_out, int out_size) {
    const float* img1 = (const float*)d_in[0];
    const float* img2 = (const float*)d_in[1];
    float* out = (float*)d_out;

    hml_zero_kernel<<<(TOTAL_HIST + 255) / 256, 256>>>();
    hml_hist_kernel<<<2 * BLOCKS_PER_IMG, THREADS>>>(img1, img2);
    hml_loss_kernel<<<1, NUM_BINS>>>(out);
}

// round 8
// speedup vs baseline: 1.0989x; 1.0989x over previous
#include <cuda_runtime.h>
#include <cuda_bf16.h>
#include <stdint.h>

#define NUM_BINS 256
#define NCH 3
#define HW (512 * 512)            // elements per (b, c) plane
#define BATCH 16
#define CHUNKS 8                  // chunks per (b,c) plane
#define CHUNK_ELEMS (HW / CHUNKS) // 32768
#define THREADS 256
#define BLOCKS_PER_IMG (BATCH * NCH * CHUNKS)   // 384
#define TOTAL_HIST (2 * NCH * NUM_BINS)         // 1536

// Zero-initialized at module load; loss kernel self-resets it after reading,
// so every kernel_launch invocation (correctness run + each graph replay)
// starts from a clean state. No separate zero kernel needed.
__device__ unsigned int g_hist[TOTAL_HIST];

__global__ __launch_bounds__(THREADS)
void hml_hist_kernel(const float* __restrict__ img1,
                     const float* __restrict__ img2) {
    // 32 bank-private copies: h[bin*32 + lane]. A warp's 32 concurrent
    // atomics always hit 32 distinct banks -> no intra-warp conflicts on the
    // shared-atomic RMW path. Only the 8 warps of the block share a column.
    __shared__ unsigned int h[NUM_BINS * 32];   // 32 KB

    for (int i = threadIdx.x; i < NUM_BINS * 32; i += THREADS) h[i] = 0u;
    __syncthreads();

    int bx  = blockIdx.x;
    int img = bx / BLOCKS_PER_IMG;            // 0 or 1
    int r   = bx - img * BLOCKS_PER_IMG;      // 0..383
    int bc    = r / CHUNKS;                   // 0..47  (b*3 + c)
    int chunk = r - bc * CHUNKS;              // 0..7
    int c = bc % NCH;

    const float* src = (img == 0) ? img1 : img2;
    const float4* p = reinterpret_cast<const float4*>(
        src + (size_t)bc * HW + (size_t)chunk * CHUNK_ELEMS);

    const int lane = threadIdx.x & 31;
    const int n4 = CHUNK_ELEMS / 4;           // 8192 float4 per block
    #pragma unroll 4
    for (int i = threadIdx.x; i < n4; i += THREADS) {
        float4 v = p[i];
        float vals[4] = {v.x, v.y, v.z, v.w};
        #pragma unroll
        for (int k = 0; k < 4; k++) {
            float x = vals[k];
            if (x >= 0.0f && x <= 1.0f) {
                int bin = (int)floorf(x * (float)NUM_BINS);
                bin = bin > (NUM_BINS - 1) ? (NUM_BINS - 1) : bin;
                atomicAdd(&h[(bin << 5) + lane], 1u);
            }
        }
    }
    __syncthreads();

    // Merge 32 columns per bin with a rotated (conflict-free) access pattern,
    // then one global atomic per bin.
    unsigned int* dst = &g_hist[(img * NCH + c) * NUM_BINS];
    int bin = threadIdx.x;
    unsigned int sum = 0u;
    #pragma unroll
    for (int j = 0; j < 32; j++)
        sum += h[(bin << 5) + ((j + bin) & 31)];
    if (sum) atomicAdd(&dst[bin], sum);
}

// 768 threads: thread t -> channel c = t>>8, bin = t&255.
// g_hist index for img0 is exactly t (c*256+bin == t), img1 is 768+t.
__global__ __launch_bounds__(768)
void hml_loss_kernel(float* __restrict__ out) {
    __shared__ float ws1[24], ws2[24];     // per-warp scan sums
    __shared__ float tot1s[NCH], tot2s[NCH];
    __shared__ float red[24];

    int t = threadIdx.x;                   // 0..767
    int lane = t & 31;
    int w = t >> 5;                        // warp 0..23 (8 warps per channel)
    int c = t >> 8;                        // channel 0..2

    float h1 = (float)g_hist[t];
    float h2 = (float)g_hist[TOTAL_HIST / 2 + t];
    // self-reset for the next replay (each thread zeroes what it read)
    g_hist[t] = 0u;
    g_hist[TOTAL_HIST / 2 + t] = 0u;

    // inclusive scan within warp
    float s1 = h1, s2 = h2;
    #pragma unroll
    for (int off = 1; off < 32; off <<= 1) {
        float a1 = __shfl_up_sync(0xFFFFFFFFu, s1, off);
        float a2 = __shfl_up_sync(0xFFFFFFFFu, s2, off);
        if (lane >= off) { s1 += a1; s2 += a2; }
    }
    if (lane == 31) { ws1[w] = s1; ws2[w] = s2; }
    __syncthreads();

    // add prefix of earlier warps within this channel
    float o1 = 0.0f, o2 = 0.0f;
    #pragma unroll
    for (int j = 0; j < 8; j++) {
        int wj = (c << 3) + j;
        if (wj < w) { o1 += ws1[wj]; o2 += ws2[wj]; }
    }
    float cdf1 = s1 + o1;
    float cdf2 = s2 + o2;

    // channel totals = cdf at last bin
    if ((t & 255) == 255) { tot1s[c] = cdf1; tot2s[c] = cdf2; }
    __syncthreads();

    float d = fabsf(cdf1 / tot1s[c] - cdf2 / tot2s[c]);

    // block reduce over 768 threads
    #pragma unroll
    for (int o = 16; o > 0; o >>= 1)
        d += __shfl_down_sync(0xFFFFFFFFu, d, o);
    if (lane == 0) red[w] = d;
    __syncthreads();
    if (t == 0) {
        float s = 0.0f;
        #pragma unroll
        for (int j = 0; j < 24; j++) s += red[j];
        out[0] = s / 3.0f;
    }
}

extern "C" void kernel_launch(void* const* d_in, const int* in_sizes, int n_in,
                              void* d_out, int out_size) {
    const float* img1 = (const float*)d_in[0];
    const float* img2 = (const float*)d_in[1];
    float* out = (float*)d_out;

    hml_hist_kernel<<<2 * BLOCKS_PER_IMG, THREADS>>>(img1, img2);
    hml_loss_kernel<<<1, 768>>>(out);
}